// round 9
// baseline (speedup 1.0000x reference)
#include <cuda_runtime.h>
#include <math.h>

// Problem constants (fixed shapes for this problem):
//   hidden_states [4,2048,1024] f32, gate_w [1024,8], w1/w3 [8,1024,4096],
//   w2 [8,4096,1024], out [4,2048,1024] f32, top_k = 2.
#define H_DIM 1024
#define E_NUM 8
#define I_DIM 4096
#define T_MAX 8192
#define CAP   T_MAX   // per-expert token capacity (worst case: all tokens)

// ---------------- scratch (device globals; no allocations allowed) ----------
__device__ int   g_top_idx[T_MAX * 2];
__device__ float g_top_w  [T_MAX * 2];
__device__ int   g_counts [E_NUM];
__device__ int   g_tok    [E_NUM * CAP];
__device__ float g_wlist  [E_NUM * CAP];
// SwiGLU intermediate h, bucketed per expert: [E][CAP][I]  (1 GiB, zero-init)
__device__ float g_h      [E_NUM * CAP * (size_t)I_DIM];

// ---------------- 1) router: logits -> softmax top-2 -> normalized weights --
// One warp per token. logits[e] = dot(x[t], gate_w[:,e]); top-2 of softmax
// normalized by their sum == 2-way softmax over the two top logits.
__global__ void router_kernel(const float* __restrict__ X,
                              const float* __restrict__ GW, int T) {
    int t    = (blockIdx.x * blockDim.x + threadIdx.x) >> 5;
    int lane = threadIdx.x & 31;
    if (t >= T) return;
    const float* xr = X + (size_t)t * H_DIM;
    float acc[E_NUM];
#pragma unroll
    for (int e = 0; e < E_NUM; ++e) acc[e] = 0.f;
    for (int k = lane; k < H_DIM; k += 32) {
        float  xv = __ldg(xr + k);
        float4 g0 = *(const float4*)(GW + (size_t)k * E_NUM);
        float4 g1 = *(const float4*)(GW + (size_t)k * E_NUM + 4);
        acc[0] += xv * g0.x; acc[1] += xv * g0.y;
        acc[2] += xv * g0.z; acc[3] += xv * g0.w;
        acc[4] += xv * g1.x; acc[5] += xv * g1.y;
        acc[6] += xv * g1.z; acc[7] += xv * g1.w;
    }
#pragma unroll
    for (int off = 16; off > 0; off >>= 1) {
#pragma unroll
        for (int e = 0; e < E_NUM; ++e)
            acc[e] += __shfl_xor_sync(0xffffffffu, acc[e], off);
    }
    if (lane == 0) {
        int i1 = 0;
#pragma unroll
        for (int e = 1; e < E_NUM; ++e) if (acc[e] > acc[i1]) i1 = e;
        int i2 = (i1 == 0) ? 1 : 0;
#pragma unroll
        for (int e = 0; e < E_NUM; ++e)
            if (e != i1 && acc[e] > acc[i2]) i2 = e;
        float d  = expf(acc[i2] - acc[i1]);    // <= 1
        float wa = 1.f / (1.f + d);
        g_top_idx[2*t]   = i1;  g_top_w[2*t]   = wa;
        g_top_idx[2*t+1] = i2;  g_top_w[2*t+1] = d / (1.f + d);
    }
}

// ---------------- 2) deterministic per-expert token compaction ---------------
// One block per expert; chunked ballot + block scan keeps token order stable.
__global__ void build_lists_kernel(int T) {
    const int e    = blockIdx.x;
    const int tid  = threadIdx.x;
    const int lane = tid & 31;
    const int wid  = tid >> 5;
    __shared__ int s_wsum[8];
    __shared__ int s_base;
    if (tid == 0) s_base = 0;
    __syncthreads();
    for (int start = 0; start < T; start += 256) {
        int   t    = start + tid;
        int   flag = 0;
        float w    = 0.f;
        if (t < T) {
            if      (g_top_idx[2*t]   == e) { flag = 1; w = g_top_w[2*t];   }
            else if (g_top_idx[2*t+1] == e) { flag = 1; w = g_top_w[2*t+1]; }
        }
        unsigned m = __ballot_sync(0xffffffffu, flag);
        if (lane == 0) s_wsum[wid] = __popc(m);
        __syncthreads();
        int off = s_base;
        for (int i = 0; i < wid; ++i) off += s_wsum[i];
        int pos = off + __popc(m & ((1u << lane) - 1u));
        if (flag) {
            g_tok  [e * CAP + pos] = t;
            g_wlist[e * CAP + pos] = w;
        }
        __syncthreads();
        if (tid == 0) {
            int tot = 0;
#pragma unroll
            for (int i = 0; i < 8; ++i) tot += s_wsum[i];
            s_base += tot;
        }
        __syncthreads();
    }
    if (tid == 0) g_counts[e] = s_base;
}

// ---------------- 3) GEMM1: h = silu(x@w1[e]) * (x@w3[e]) -------------------
// Dual-B GEMM: A tile (gathered x rows) shared between w1 and w3 products.
// BM=128, BN=64, BK=16, 256 threads, 8x4 per thread per matrix, double buffer.
#define BM1 128
#define BN1 64
#define BK1 16

__global__ void __launch_bounds__(256, 2)
moe_gemm1_kernel(const float* __restrict__ X,
                 const float* __restrict__ W1,
                 const float* __restrict__ W3) {
    const int e   = blockIdx.z;
    const int cnt = g_counts[e];
    const int m0  = blockIdx.y * BM1;
    if (m0 >= cnt) return;
    const int n0  = blockIdx.x * BN1;
    const int tid = threadIdx.x;

    __shared__ float As [2][BK1][BM1];
    __shared__ float B1s[2][BK1][BN1];
    __shared__ float B3s[2][BK1][BN1];
    __shared__ int   s_tok[BM1];

    if (tid < BM1) {
        int r = m0 + tid;
        s_tok[tid] = g_tok[e * CAP + (r < cnt ? r : 0)];  // cnt>0 guaranteed
    }
    __syncthreads();

    const float* B1p = W1 + (size_t)e * H_DIM * I_DIM + n0;
    const float* B3p = W3 + (size_t)e * H_DIM * I_DIM + n0;

    // A loads: thread covers row ar, float4 columns akq and akq+2 (BK1=16)
    const int    ar   = tid & 127;
    const int    akq  = tid >> 7;     // 0/1
    const float* Arow = X + (size_t)s_tok[ar] * H_DIM;

    // B loads: one float4 per matrix per thread
    const int bk = tid >> 4;          // 0..15
    const int bn = (tid & 15) * 4;    // 0..60

    const int ty = tid >> 4;          // 0..15 -> 8 rows each
    const int tx = tid & 15;          // 0..15 -> 4 cols each

    float acc1[8][4], acc3[8][4];
#pragma unroll
    for (int i = 0; i < 8; ++i)
#pragma unroll
        for (int j = 0; j < 4; ++j) { acc1[i][j] = 0.f; acc3[i][j] = 0.f; }

    float4 av0, av1, bv1, bv3;
    av0 = *(const float4*)(Arow + akq * 4);
    av1 = *(const float4*)(Arow + (akq + 2) * 4);
    bv1 = *(const float4*)(B1p + (size_t)bk * I_DIM + bn);
    bv3 = *(const float4*)(B3p + (size_t)bk * I_DIM + bn);
    As[0][akq*4+0][ar] = av0.x; As[0][akq*4+1][ar] = av0.y;
    As[0][akq*4+2][ar] = av0.z; As[0][akq*4+3][ar] = av0.w;
    As[0][(akq+2)*4+0][ar] = av1.x; As[0][(akq+2)*4+1][ar] = av1.y;
    As[0][(akq+2)*4+2][ar] = av1.z; As[0][(akq+2)*4+3][ar] = av1.w;
    *(float4*)&B1s[0][bk][bn] = bv1;
    *(float4*)&B3s[0][bk][bn] = bv3;
    __syncthreads();

    const int KT = H_DIM / BK1;   // 64
    for (int kt = 0; kt < KT; ++kt) {
        const int buf = kt & 1;
        if (kt + 1 < KT) {
            const int k1 = (kt + 1) * BK1;
            av0 = *(const float4*)(Arow + k1 + akq * 4);
            av1 = *(const float4*)(Arow + k1 + (akq + 2) * 4);
            bv1 = *(const float4*)(B1p + (size_t)(k1 + bk) * I_DIM + bn);
            bv3 = *(const float4*)(B3p + (size_t)(k1 + bk) * I_DIM + bn);
        }
#pragma unroll
        for (int kk = 0; kk < BK1; ++kk) {
            float4 a03 = *(const float4*)&As [buf][kk][ty * 8];
            float4 a47 = *(const float4*)&As [buf][kk][ty * 8 + 4];
            float4 b1  = *(const float4*)&B1s[buf][kk][tx * 4];
            float4 b3  = *(const float4*)&B3s[buf][kk][tx * 4];
            float a[8]  = {a03.x,a03.y,a03.z,a03.w,a47.x,a47.y,a47.z,a47.w};
            float c1[4] = {b1.x,b1.y,b1.z,b1.w};
            float c3[4] = {b3.x,b3.y,b3.z,b3.w};
#pragma unroll
            for (int i = 0; i < 8; ++i)
#pragma unroll
                for (int j = 0; j < 4; ++j) {
                    acc1[i][j] = fmaf(a[i], c1[j], acc1[i][j]);
                    acc3[i][j] = fmaf(a[i], c3[j], acc3[i][j]);
                }
        }
        if (kt + 1 < KT) {
            const int nb = buf ^ 1;
            As[nb][akq*4+0][ar] = av0.x; As[nb][akq*4+1][ar] = av0.y;
            As[nb][akq*4+2][ar] = av0.z; As[nb][akq*4+3][ar] = av0.w;
            As[nb][(akq+2)*4+0][ar] = av1.x; As[nb][(akq+2)*4+1][ar] = av1.y;
            As[nb][(akq+2)*4+2][ar] = av1.z; As[nb][(akq+2)*4+3][ar] = av1.w;
            *(float4*)&B1s[nb][bk][bn] = bv1;
            *(float4*)&B3s[nb][bk][bn] = bv3;
        }
        __syncthreads();
    }

    // SwiGLU epilogue -> g_h
#pragma unroll
    for (int i = 0; i < 8; ++i) {
        const int r = ty * 8 + i;
        if (m0 + r < cnt) {
            float* hp = g_h + ((size_t)e * CAP + m0 + r) * I_DIM + n0 + tx * 4;
            float4 o;
            float a0 = acc1[i][0], a1 = acc1[i][1];
            float a2 = acc1[i][2], a3 = acc1[i][3];
            o.x = (a0 / (1.f + expf(-a0))) * acc3[i][0];
            o.y = (a1 / (1.f + expf(-a1))) * acc3[i][1];
            o.z = (a2 / (1.f + expf(-a2))) * acc3[i][2];
            o.w = (a3 / (1.f + expf(-a3))) * acc3[i][3];
            *(float4*)hp = o;
        }
    }
}

// ---------------- 4) GEMM2: out[tok] += w * (h @ w2[e]) ----------------------
// BM=128, BN=128, BK=8, 256 threads, 8x8 per thread, double buffer.
// Scatter via atomicAdd: exactly two commutative adds per out element.
#define BM2 128
#define BN2 128
#define BK2 8

__global__ void __launch_bounds__(256, 2)
moe_gemm2_kernel(const float* __restrict__ W2, float* __restrict__ Out) {
    const int e   = blockIdx.z;
    const int cnt = g_counts[e];
    const int m0  = blockIdx.y * BM2;
    if (m0 >= cnt) return;
    const int n0  = blockIdx.x * BN2;
    const int tid = threadIdx.x;

    __shared__ float As[2][BK2][BM2];
    __shared__ float Bs[2][BK2][BN2];
    __shared__ int   s_tok[BM2];
    __shared__ float s_w  [BM2];

    if (tid < BM2) {
        int  r = m0 + tid;
        bool v = r < cnt;
        s_tok[tid] = v ? g_tok  [e * CAP + r] : 0;
        s_w  [tid] = v ? g_wlist[e * CAP + r] : 0.f;
    }

    const float* Ap = g_h + ((size_t)e * CAP + m0) * I_DIM;
    const float* Bp = W2 + (size_t)e * I_DIM * H_DIM + n0;

    const int ar  = tid & 127;
    const int akq = tid >> 7;       // 0/1 (row has 2 float4 for BK2=8)
    const int bk  = tid >> 5;       // 0..7
    const int bn  = (tid & 31) * 4; // 0..124

    const int ty = tid >> 4;
    const int tx = tid & 15;

    float acc[8][8];
#pragma unroll
    for (int i = 0; i < 8; ++i)
#pragma unroll
        for (int j = 0; j < 8; ++j) acc[i][j] = 0.f;

    float4 av, bv;
    av = *(const float4*)(Ap + (size_t)ar * I_DIM + akq * 4);
    bv = *(const float4*)(Bp + (size_t)bk * H_DIM + bn);
    As[0][akq*4+0][ar] = av.x; As[0][akq*4+1][ar] = av.y;
    As[0][akq*4+2][ar] = av.z; As[0][akq*4+3][ar] = av.w;
    *(float4*)&Bs[0][bk][bn] = bv;
    __syncthreads();

    const int KT = I_DIM / BK2;   // 512
    for (int kt = 0; kt < KT; ++kt) {
        const int buf = kt & 1;
        if (kt + 1 < KT) {
            const int k1 = (kt + 1) * BK2;
            av = *(const float4*)(Ap + (size_t)ar * I_DIM + k1 + akq * 4);
            bv = *(const float4*)(Bp + (size_t)(k1 + bk) * H_DIM + bn);
        }
#pragma unroll
        for (int kk = 0; kk < BK2; ++kk) {
            float4 a03 = *(const float4*)&As[buf][kk][ty * 8];
            float4 a47 = *(const float4*)&As[buf][kk][ty * 8 + 4];
            float4 b03 = *(const float4*)&Bs[buf][kk][tx * 8];
            float4 b47 = *(const float4*)&Bs[buf][kk][tx * 8 + 4];
            float a[8] = {a03.x,a03.y,a03.z,a03.w,a47.x,a47.y,a47.z,a47.w};
            float b[8] = {b03.x,b03.y,b03.z,b03.w,b47.x,b47.y,b47.z,b47.w};
#pragma unroll
            for (int i = 0; i < 8; ++i)
#pragma unroll
                for (int j = 0; j < 8; ++j)
                    acc[i][j] = fmaf(a[i], b[j], acc[i][j]);
        }
        if (kt + 1 < KT) {
            const int nb = buf ^ 1;
            As[nb][akq*4+0][ar] = av.x; As[nb][akq*4+1][ar] = av.y;
            As[nb][akq*4+2][ar] = av.z; As[nb][akq*4+3][ar] = av.w;
            *(float4*)&Bs[nb][bk][bn] = bv;
        }
        __syncthreads();
    }

#pragma unroll
    for (int i = 0; i < 8; ++i) {
        const int r = ty * 8 + i;
        if (m0 + r < cnt) {
            const float w  = s_w[r];
            float*      op = Out + (size_t)s_tok[r] * H_DIM + n0 + tx * 8;
#pragma unroll
            for (int j = 0; j < 8; ++j)
                atomicAdd(op + j, acc[i][j] * w);
        }
    }
}

// ---------------- launch ----------------------------------------------------
extern "C" void kernel_launch(void* const* d_in, const int* in_sizes, int n_in,
                              void* d_out, int out_size) {
    const float* x  = (const float*)d_in[0];
    const float* gw = (const float*)d_in[1];
    const float* w1 = (const float*)d_in[2];
    const float* w3 = (const float*)d_in[3];
    const float* w2 = (const float*)d_in[4];
    float* out = (float*)d_out;
    const int T = in_sizes[0] / H_DIM;

    cudaMemsetAsync(d_out, 0, (size_t)out_size * sizeof(float), 0);
    router_kernel<<<(T + 7) / 8, 256>>>(x, gw, T);
    build_lists_kernel<<<E_NUM, 256>>>(T);
    dim3 g1(I_DIM / BN1, (T + BM1 - 1) / BM1, E_NUM);
    moe_gemm1_kernel<<<g1, 256>>>(x, w1, w3);
    dim3 g2(H_DIM / BN2, (T + BM2 - 1) / BM2, E_NUM);
    moe_gemm2_kernel<<<g2, 256>>>(w2, out);
}

// round 10
// speedup vs baseline: 1.0010x; 1.0010x over previous
#include <cuda_runtime.h>
#include <math.h>

// Problem constants (fixed shapes for this problem):
//   hidden_states [4,2048,1024] f32, gate_w [1024,8], w1/w3 [8,1024,4096],
//   w2 [8,4096,1024], out [4,2048,1024] f32, top_k = 2.
#define H_DIM 1024
#define E_NUM 8
#define I_DIM 4096
#define T_MAX 8192
#define CAP   T_MAX   // per-expert token capacity (worst case: all tokens)

// ---------------- scratch (device globals; no allocations allowed) ----------
__device__ int   g_top_idx[T_MAX * 2];
__device__ float g_top_w  [T_MAX * 2];
__device__ int   g_counts [E_NUM];
__device__ int   g_tok    [E_NUM * CAP];
__device__ float g_wlist  [E_NUM * CAP];
// SwiGLU intermediate h, bucketed per expert: [E][CAP][I]  (1 GiB, zero-init)
__device__ float g_h      [E_NUM * CAP * (size_t)I_DIM];

// ---------------- 1) router: logits -> softmax top-2 -> normalized weights --
// One warp per token. logits[e] = dot(x[t], gate_w[:,e]); top-2 of softmax
// normalized by their sum == 2-way softmax over the two top logits.
__global__ void router_kernel(const float* __restrict__ X,
                              const float* __restrict__ GW, int T) {
    int t    = (blockIdx.x * blockDim.x + threadIdx.x) >> 5;
    int lane = threadIdx.x & 31;
    if (t >= T) return;
    const float* xr = X + (size_t)t * H_DIM;
    float acc[E_NUM];
#pragma unroll
    for (int e = 0; e < E_NUM; ++e) acc[e] = 0.f;
    for (int k = lane; k < H_DIM; k += 32) {
        float  xv = __ldg(xr + k);
        float4 g0 = *(const float4*)(GW + (size_t)k * E_NUM);
        float4 g1 = *(const float4*)(GW + (size_t)k * E_NUM + 4);
        acc[0] += xv * g0.x; acc[1] += xv * g0.y;
        acc[2] += xv * g0.z; acc[3] += xv * g0.w;
        acc[4] += xv * g1.x; acc[5] += xv * g1.y;
        acc[6] += xv * g1.z; acc[7] += xv * g1.w;
    }
#pragma unroll
    for (int off = 16; off > 0; off >>= 1) {
#pragma unroll
        for (int e = 0; e < E_NUM; ++e)
            acc[e] += __shfl_xor_sync(0xffffffffu, acc[e], off);
    }
    if (lane == 0) {
        int i1 = 0;
#pragma unroll
        for (int e = 1; e < E_NUM; ++e) if (acc[e] > acc[i1]) i1 = e;
        int i2 = (i1 == 0) ? 1 : 0;
#pragma unroll
        for (int e = 0; e < E_NUM; ++e)
            if (e != i1 && acc[e] > acc[i2]) i2 = e;
        float d  = expf(acc[i2] - acc[i1]);    // <= 1
        float wa = 1.f / (1.f + d);
        g_top_idx[2*t]   = i1;  g_top_w[2*t]   = wa;
        g_top_idx[2*t+1] = i2;  g_top_w[2*t+1] = d / (1.f + d);
    }
}

// ---------------- 2) deterministic per-expert token compaction ---------------
// One block per expert; chunked ballot + block scan keeps token order stable.
__global__ void build_lists_kernel(int T) {
    const int e    = blockIdx.x;
    const int tid  = threadIdx.x;
    const int lane = tid & 31;
    const int wid  = tid >> 5;
    __shared__ int s_wsum[8];
    __shared__ int s_base;
    if (tid == 0) s_base = 0;
    __syncthreads();
    for (int start = 0; start < T; start += 256) {
        int   t    = start + tid;
        int   flag = 0;
        float w    = 0.f;
        if (t < T) {
            if      (g_top_idx[2*t]   == e) { flag = 1; w = g_top_w[2*t];   }
            else if (g_top_idx[2*t+1] == e) { flag = 1; w = g_top_w[2*t+1]; }
        }
        unsigned m = __ballot_sync(0xffffffffu, flag);
        if (lane == 0) s_wsum[wid] = __popc(m);
        __syncthreads();
        int off = s_base;
        for (int i = 0; i < wid; ++i) off += s_wsum[i];
        int pos = off + __popc(m & ((1u << lane) - 1u));
        if (flag) {
            g_tok  [e * CAP + pos] = t;
            g_wlist[e * CAP + pos] = w;
        }
        __syncthreads();
        if (tid == 0) {
            int tot = 0;
#pragma unroll
            for (int i = 0; i < 8; ++i) tot += s_wsum[i];
            s_base += tot;
        }
        __syncthreads();
    }
    if (tid == 0) g_counts[e] = s_base;
}

// ---------------- 3) GEMM1: h = silu(x@w1[e]) * (x@w3[e]) -------------------
// Dual-B GEMM: A tile (gathered x rows) shared between w1 and w3 products.
// BM=128, BN=64, BK=16, 256 threads, 8x4 per thread per matrix, double buffer.
#define BM1 128
#define BN1 64
#define BK1 16

__global__ void __launch_bounds__(256, 2)
moe_gemm1_kernel(const float* __restrict__ X,
                 const float* __restrict__ W1,
                 const float* __restrict__ W3) {
    const int e   = blockIdx.z;
    const int cnt = g_counts[e];
    const int m0  = blockIdx.y * BM1;
    if (m0 >= cnt) return;
    const int n0  = blockIdx.x * BN1;
    const int tid = threadIdx.x;

    __shared__ float As [2][BK1][BM1];
    __shared__ float B1s[2][BK1][BN1];
    __shared__ float B3s[2][BK1][BN1];
    __shared__ int   s_tok[BM1];

    if (tid < BM1) {
        int r = m0 + tid;
        s_tok[tid] = g_tok[e * CAP + (r < cnt ? r : 0)];  // cnt>0 guaranteed
    }
    __syncthreads();

    const float* B1p = W1 + (size_t)e * H_DIM * I_DIM + n0;
    const float* B3p = W3 + (size_t)e * H_DIM * I_DIM + n0;

    // A loads: thread covers row ar, float4 columns akq and akq+2 (BK1=16)
    const int    ar   = tid & 127;
    const int    akq  = tid >> 7;     // 0/1
    const float* Arow = X + (size_t)s_tok[ar] * H_DIM;

    // B loads: one float4 per matrix per thread
    const int bk = tid >> 4;          // 0..15
    const int bn = (tid & 15) * 4;    // 0..60

    const int ty = tid >> 4;          // 0..15 -> 8 rows each
    const int tx = tid & 15;          // 0..15 -> 4 cols each

    float acc1[8][4], acc3[8][4];
#pragma unroll
    for (int i = 0; i < 8; ++i)
#pragma unroll
        for (int j = 0; j < 4; ++j) { acc1[i][j] = 0.f; acc3[i][j] = 0.f; }

    float4 av0, av1, bv1, bv3;
    av0 = *(const float4*)(Arow + akq * 4);
    av1 = *(const float4*)(Arow + (akq + 2) * 4);
    bv1 = *(const float4*)(B1p + (size_t)bk * I_DIM + bn);
    bv3 = *(const float4*)(B3p + (size_t)bk * I_DIM + bn);
    As[0][akq*4+0][ar] = av0.x; As[0][akq*4+1][ar] = av0.y;
    As[0][akq*4+2][ar] = av0.z; As[0][akq*4+3][ar] = av0.w;
    As[0][(akq+2)*4+0][ar] = av1.x; As[0][(akq+2)*4+1][ar] = av1.y;
    As[0][(akq+2)*4+2][ar] = av1.z; As[0][(akq+2)*4+3][ar] = av1.w;
    *(float4*)&B1s[0][bk][bn] = bv1;
    *(float4*)&B3s[0][bk][bn] = bv3;
    __syncthreads();

    const int KT = H_DIM / BK1;   // 64
    for (int kt = 0; kt < KT; ++kt) {
        const int buf = kt & 1;
        if (kt + 1 < KT) {
            const int k1 = (kt + 1) * BK1;
            av0 = *(const float4*)(Arow + k1 + akq * 4);
            av1 = *(const float4*)(Arow + k1 + (akq + 2) * 4);
            bv1 = *(const float4*)(B1p + (size_t)(k1 + bk) * I_DIM + bn);
            bv3 = *(const float4*)(B3p + (size_t)(k1 + bk) * I_DIM + bn);
        }
#pragma unroll
        for (int kk = 0; kk < BK1; ++kk) {
            float4 a03 = *(const float4*)&As [buf][kk][ty * 8];
            float4 a47 = *(const float4*)&As [buf][kk][ty * 8 + 4];
            float4 b1  = *(const float4*)&B1s[buf][kk][tx * 4];
            float4 b3  = *(const float4*)&B3s[buf][kk][tx * 4];
            float a[8]  = {a03.x,a03.y,a03.z,a03.w,a47.x,a47.y,a47.z,a47.w};
            float c1[4] = {b1.x,b1.y,b1.z,b1.w};
            float c3[4] = {b3.x,b3.y,b3.z,b3.w};
#pragma unroll
            for (int i = 0; i < 8; ++i)
#pragma unroll
                for (int j = 0; j < 4; ++j) {
                    acc1[i][j] = fmaf(a[i], c1[j], acc1[i][j]);
                    acc3[i][j] = fmaf(a[i], c3[j], acc3[i][j]);
                }
        }
        if (kt + 1 < KT) {
            const int nb = buf ^ 1;
            As[nb][akq*4+0][ar] = av0.x; As[nb][akq*4+1][ar] = av0.y;
            As[nb][akq*4+2][ar] = av0.z; As[nb][akq*4+3][ar] = av0.w;
            As[nb][(akq+2)*4+0][ar] = av1.x; As[nb][(akq+2)*4+1][ar] = av1.y;
            As[nb][(akq+2)*4+2][ar] = av1.z; As[nb][(akq+2)*4+3][ar] = av1.w;
            *(float4*)&B1s[nb][bk][bn] = bv1;
            *(float4*)&B3s[nb][bk][bn] = bv3;
        }
        __syncthreads();
    }

    // SwiGLU epilogue -> g_h
#pragma unroll
    for (int i = 0; i < 8; ++i) {
        const int r = ty * 8 + i;
        if (m0 + r < cnt) {
            float* hp = g_h + ((size_t)e * CAP + m0 + r) * I_DIM + n0 + tx * 4;
            float4 o;
            float a0 = acc1[i][0], a1 = acc1[i][1];
            float a2 = acc1[i][2], a3 = acc1[i][3];
            o.x = (a0 / (1.f + expf(-a0))) * acc3[i][0];
            o.y = (a1 / (1.f + expf(-a1))) * acc3[i][1];
            o.z = (a2 / (1.f + expf(-a2))) * acc3[i][2];
            o.w = (a3 / (1.f + expf(-a3))) * acc3[i][3];
            *(float4*)hp = o;
        }
    }
}

// ---------------- 4) GEMM2: out[tok] += w * (h @ w2[e]) ----------------------
// BM=128, BN=128, BK=8, 256 threads, 8x8 per thread, double buffer.
// Scatter via atomicAdd: exactly two commutative adds per out element.
#define BM2 128
#define BN2 128
#define BK2 8

__global__ void __launch_bounds__(256, 2)
moe_gemm2_kernel(const float* __restrict__ W2, float* __restrict__ Out) {
    const int e   = blockIdx.z;
    const int cnt = g_counts[e];
    const int m0  = blockIdx.y * BM2;
    if (m0 >= cnt) return;
    const int n0  = blockIdx.x * BN2;
    const int tid = threadIdx.x;

    __shared__ float As[2][BK2][BM2];
    __shared__ float Bs[2][BK2][BN2];
    __shared__ int   s_tok[BM2];
    __shared__ float s_w  [BM2];

    if (tid < BM2) {
        int  r = m0 + tid;
        bool v = r < cnt;
        s_tok[tid] = v ? g_tok  [e * CAP + r] : 0;
        s_w  [tid] = v ? g_wlist[e * CAP + r] : 0.f;
    }

    const float* Ap = g_h + ((size_t)e * CAP + m0) * I_DIM;
    const float* Bp = W2 + (size_t)e * I_DIM * H_DIM + n0;

    const int ar  = tid & 127;
    const int akq = tid >> 7;       // 0/1 (row has 2 float4 for BK2=8)
    const int bk  = tid >> 5;       // 0..7
    const int bn  = (tid & 31) * 4; // 0..124

    const int ty = tid >> 4;
    const int tx = tid & 15;

    float acc[8][8];
#pragma unroll
    for (int i = 0; i < 8; ++i)
#pragma unroll
        for (int j = 0; j < 8; ++j) acc[i][j] = 0.f;

    float4 av, bv;
    av = *(const float4*)(Ap + (size_t)ar * I_DIM + akq * 4);
    bv = *(const float4*)(Bp + (size_t)bk * H_DIM + bn);
    As[0][akq*4+0][ar] = av.x; As[0][akq*4+1][ar] = av.y;
    As[0][akq*4+2][ar] = av.z; As[0][akq*4+3][ar] = av.w;
    *(float4*)&Bs[0][bk][bn] = bv;
    __syncthreads();

    const int KT = I_DIM / BK2;   // 512
    for (int kt = 0; kt < KT; ++kt) {
        const int buf = kt & 1;
        if (kt + 1 < KT) {
            const int k1 = (kt + 1) * BK2;
            av = *(const float4*)(Ap + (size_t)ar * I_DIM + k1 + akq * 4);
            bv = *(const float4*)(Bp + (size_t)(k1 + bk) * H_DIM + bn);
        }
#pragma unroll
        for (int kk = 0; kk < BK2; ++kk) {
            float4 a03 = *(const float4*)&As[buf][kk][ty * 8];
            float4 a47 = *(const float4*)&As[buf][kk][ty * 8 + 4];
            float4 b03 = *(const float4*)&Bs[buf][kk][tx * 8];
            float4 b47 = *(const float4*)&Bs[buf][kk][tx * 8 + 4];
            float a[8] = {a03.x,a03.y,a03.z,a03.w,a47.x,a47.y,a47.z,a47.w};
            float b[8] = {b03.x,b03.y,b03.z,b03.w,b47.x,b47.y,b47.z,b47.w};
#pragma unroll
            for (int i = 0; i < 8; ++i)
#pragma unroll
                for (int j = 0; j < 8; ++j)
                    acc[i][j] = fmaf(a[i], b[j], acc[i][j]);
        }
        if (kt + 1 < KT) {
            const int nb = buf ^ 1;
            As[nb][akq*4+0][ar] = av.x; As[nb][akq*4+1][ar] = av.y;
            As[nb][akq*4+2][ar] = av.z; As[nb][akq*4+3][ar] = av.w;
            *(float4*)&Bs[nb][bk][bn] = bv;
        }
        __syncthreads();
    }

#pragma unroll
    for (int i = 0; i < 8; ++i) {
        const int r = ty * 8 + i;
        if (m0 + r < cnt) {
            const float w  = s_w[r];
            float*      op = Out + (size_t)s_tok[r] * H_DIM + n0 + tx * 8;
#pragma unroll
            for (int j = 0; j < 8; ++j)
                atomicAdd(op + j, acc[i][j] * w);
        }
    }
}

// ---------------- launch ----------------------------------------------------
extern "C" void kernel_launch(void* const* d_in, const int* in_sizes, int n_in,
                              void* d_out, int out_size) {
    const float* x  = (const float*)d_in[0];
    const float* gw = (const float*)d_in[1];
    const float* w1 = (const float*)d_in[2];
    const float* w3 = (const float*)d_in[3];
    const float* w2 = (const float*)d_in[4];
    float* out = (float*)d_out;
    const int T = in_sizes[0] / H_DIM;

    cudaMemsetAsync(d_out, 0, (size_t)out_size * sizeof(float), 0);
    router_kernel<<<(T + 7) / 8, 256>>>(x, gw, T);
    build_lists_kernel<<<E_NUM, 256>>>(T);
    dim3 g1(I_DIM / BN1, (T + BM1 - 1) / BM1, E_NUM);
    moe_gemm1_kernel<<<g1, 256>>>(x, w1, w3);
    dim3 g2(H_DIM / BN2, (T + BM2 - 1) / BM2, E_NUM);
    moe_gemm2_kernel<<<g2, 256>>>(w2, out);
}

// round 11
// speedup vs baseline: 1.0015x; 1.0005x over previous
#include <cuda_runtime.h>
#include <math.h>

// Problem constants (fixed shapes for this problem):
//   hidden_states [4,2048,1024] f32, gate_w [1024,8], w1/w3 [8,1024,4096],
//   w2 [8,4096,1024], out [4,2048,1024] f32, top_k = 2.
#define H_DIM 1024
#define E_NUM 8
#define I_DIM 4096
#define T_MAX 8192
#define CAP   T_MAX   // per-expert token capacity (worst case: all tokens)

// ---------------- scratch (device globals; no allocations allowed) ----------
__device__ int   g_top_idx[T_MAX * 2];
__device__ float g_top_w  [T_MAX * 2];
__device__ int   g_counts [E_NUM];
__device__ int   g_tok    [E_NUM * CAP];
__device__ float g_wlist  [E_NUM * CAP];
// SwiGLU intermediate h, bucketed per expert: [E][CAP][I]  (1 GiB, zero-init)
__device__ float g_h      [E_NUM * CAP * (size_t)I_DIM];

// ---------------- 1) router: logits -> softmax top-2 -> normalized weights --
// One warp per token. logits[e] = dot(x[t], gate_w[:,e]); top-2 of softmax
// normalized by their sum == 2-way softmax over the two top logits.
__global__ void router_kernel(const float* __restrict__ X,
                              const float* __restrict__ GW, int T) {
    int t    = (blockIdx.x * blockDim.x + threadIdx.x) >> 5;
    int lane = threadIdx.x & 31;
    if (t >= T) return;
    const float* xr = X + (size_t)t * H_DIM;
    float acc[E_NUM];
#pragma unroll
    for (int e = 0; e < E_NUM; ++e) acc[e] = 0.f;
    for (int k = lane; k < H_DIM; k += 32) {
        float  xv = __ldg(xr + k);
        float4 g0 = *(const float4*)(GW + (size_t)k * E_NUM);
        float4 g1 = *(const float4*)(GW + (size_t)k * E_NUM + 4);
        acc[0] += xv * g0.x; acc[1] += xv * g0.y;
        acc[2] += xv * g0.z; acc[3] += xv * g0.w;
        acc[4] += xv * g1.x; acc[5] += xv * g1.y;
        acc[6] += xv * g1.z; acc[7] += xv * g1.w;
    }
#pragma unroll
    for (int off = 16; off > 0; off >>= 1) {
#pragma unroll
        for (int e = 0; e < E_NUM; ++e)
            acc[e] += __shfl_xor_sync(0xffffffffu, acc[e], off);
    }
    if (lane == 0) {
        int i1 = 0;
#pragma unroll
        for (int e = 1; e < E_NUM; ++e) if (acc[e] > acc[i1]) i1 = e;
        int i2 = (i1 == 0) ? 1 : 0;
#pragma unroll
        for (int e = 0; e < E_NUM; ++e)
            if (e != i1 && acc[e] > acc[i2]) i2 = e;
        float d  = expf(acc[i2] - acc[i1]);    // <= 1
        float wa = 1.f / (1.f + d);
        g_top_idx[2*t]   = i1;  g_top_w[2*t]   = wa;
        g_top_idx[2*t+1] = i2;  g_top_w[2*t+1] = d / (1.f + d);
    }
}

// ---------------- 2) deterministic per-expert token compaction ---------------
// One block per expert; chunked ballot + block scan keeps token order stable.
__global__ void build_lists_kernel(int T) {
    const int e    = blockIdx.x;
    const int tid  = threadIdx.x;
    const int lane = tid & 31;
    const int wid  = tid >> 5;
    __shared__ int s_wsum[8];
    __shared__ int s_base;
    if (tid == 0) s_base = 0;
    __syncthreads();
    for (int start = 0; start < T; start += 256) {
        int   t    = start + tid;
        int   flag = 0;
        float w    = 0.f;
        if (t < T) {
            if      (g_top_idx[2*t]   == e) { flag = 1; w = g_top_w[2*t];   }
            else if (g_top_idx[2*t+1] == e) { flag = 1; w = g_top_w[2*t+1]; }
        }
        unsigned m = __ballot_sync(0xffffffffu, flag);
        if (lane == 0) s_wsum[wid] = __popc(m);
        __syncthreads();
        int off = s_base;
        for (int i = 0; i < wid; ++i) off += s_wsum[i];
        int pos = off + __popc(m & ((1u << lane) - 1u));
        if (flag) {
            g_tok  [e * CAP + pos] = t;
            g_wlist[e * CAP + pos] = w;
        }
        __syncthreads();
        if (tid == 0) {
            int tot = 0;
#pragma unroll
            for (int i = 0; i < 8; ++i) tot += s_wsum[i];
            s_base += tot;
        }
        __syncthreads();
    }
    if (tid == 0) g_counts[e] = s_base;
}

// ---------------- 3) GEMM1: h = silu(x@w1[e]) * (x@w3[e]) -------------------
// Dual-B GEMM: A tile (gathered x rows) shared between w1 and w3 products.
// BM=128, BN=64, BK=16, 256 threads, 8x4 per thread per matrix, double buffer.
#define BM1 128
#define BN1 64
#define BK1 16

__global__ void __launch_bounds__(256, 2)
moe_gemm1_kernel(const float* __restrict__ X,
                 const float* __restrict__ W1,
                 const float* __restrict__ W3) {
    const int e   = blockIdx.z;
    const int cnt = g_counts[e];
    const int m0  = blockIdx.y * BM1;
    if (m0 >= cnt) return;
    const int n0  = blockIdx.x * BN1;
    const int tid = threadIdx.x;

    __shared__ float As [2][BK1][BM1];
    __shared__ float B1s[2][BK1][BN1];
    __shared__ float B3s[2][BK1][BN1];
    __shared__ int   s_tok[BM1];

    if (tid < BM1) {
        int r = m0 + tid;
        s_tok[tid] = g_tok[e * CAP + (r < cnt ? r : 0)];  // cnt>0 guaranteed
    }
    __syncthreads();

    const float* B1p = W1 + (size_t)e * H_DIM * I_DIM + n0;
    const float* B3p = W3 + (size_t)e * H_DIM * I_DIM + n0;

    // A loads: thread covers row ar, float4 columns akq and akq+2 (BK1=16)
    const int    ar   = tid & 127;
    const int    akq  = tid >> 7;     // 0/1
    const float* Arow = X + (size_t)s_tok[ar] * H_DIM;

    // B loads: one float4 per matrix per thread
    const int bk = tid >> 4;          // 0..15
    const int bn = (tid & 15) * 4;    // 0..60

    const int ty = tid >> 4;          // 0..15 -> 8 rows each
    const int tx = tid & 15;          // 0..15 -> 4 cols each

    float acc1[8][4], acc3[8][4];
#pragma unroll
    for (int i = 0; i < 8; ++i)
#pragma unroll
        for (int j = 0; j < 4; ++j) { acc1[i][j] = 0.f; acc3[i][j] = 0.f; }

    float4 av0, av1, bv1, bv3;
    av0 = *(const float4*)(Arow + akq * 4);
    av1 = *(const float4*)(Arow + (akq + 2) * 4);
    bv1 = *(const float4*)(B1p + (size_t)bk * I_DIM + bn);
    bv3 = *(const float4*)(B3p + (size_t)bk * I_DIM + bn);
    As[0][akq*4+0][ar] = av0.x; As[0][akq*4+1][ar] = av0.y;
    As[0][akq*4+2][ar] = av0.z; As[0][akq*4+3][ar] = av0.w;
    As[0][(akq+2)*4+0][ar] = av1.x; As[0][(akq+2)*4+1][ar] = av1.y;
    As[0][(akq+2)*4+2][ar] = av1.z; As[0][(akq+2)*4+3][ar] = av1.w;
    *(float4*)&B1s[0][bk][bn] = bv1;
    *(float4*)&B3s[0][bk][bn] = bv3;
    __syncthreads();

    const int KT = H_DIM / BK1;   // 64
    for (int kt = 0; kt < KT; ++kt) {
        const int buf = kt & 1;
        if (kt + 1 < KT) {
            const int k1 = (kt + 1) * BK1;
            av0 = *(const float4*)(Arow + k1 + akq * 4);
            av1 = *(const float4*)(Arow + k1 + (akq + 2) * 4);
            bv1 = *(const float4*)(B1p + (size_t)(k1 + bk) * I_DIM + bn);
            bv3 = *(const float4*)(B3p + (size_t)(k1 + bk) * I_DIM + bn);
        }
#pragma unroll
        for (int kk = 0; kk < BK1; ++kk) {
            float4 a03 = *(const float4*)&As [buf][kk][ty * 8];
            float4 a47 = *(const float4*)&As [buf][kk][ty * 8 + 4];
            float4 b1  = *(const float4*)&B1s[buf][kk][tx * 4];
            float4 b3  = *(const float4*)&B3s[buf][kk][tx * 4];
            float a[8]  = {a03.x,a03.y,a03.z,a03.w,a47.x,a47.y,a47.z,a47.w};
            float c1[4] = {b1.x,b1.y,b1.z,b1.w};
            float c3[4] = {b3.x,b3.y,b3.z,b3.w};
#pragma unroll
            for (int i = 0; i < 8; ++i)
#pragma unroll
                for (int j = 0; j < 4; ++j) {
                    acc1[i][j] = fmaf(a[i], c1[j], acc1[i][j]);
                    acc3[i][j] = fmaf(a[i], c3[j], acc3[i][j]);
                }
        }
        if (kt + 1 < KT) {
            const int nb = buf ^ 1;
            As[nb][akq*4+0][ar] = av0.x; As[nb][akq*4+1][ar] = av0.y;
            As[nb][akq*4+2][ar] = av0.z; As[nb][akq*4+3][ar] = av0.w;
            As[nb][(akq+2)*4+0][ar] = av1.x; As[nb][(akq+2)*4+1][ar] = av1.y;
            As[nb][(akq+2)*4+2][ar] = av1.z; As[nb][(akq+2)*4+3][ar] = av1.w;
            *(float4*)&B1s[nb][bk][bn] = bv1;
            *(float4*)&B3s[nb][bk][bn] = bv3;
        }
        __syncthreads();
    }

    // SwiGLU epilogue -> g_h
#pragma unroll
    for (int i = 0; i < 8; ++i) {
        const int r = ty * 8 + i;
        if (m0 + r < cnt) {
            float* hp = g_h + ((size_t)e * CAP + m0 + r) * I_DIM + n0 + tx * 4;
            float4 o;
            float a0 = acc1[i][0], a1 = acc1[i][1];
            float a2 = acc1[i][2], a3 = acc1[i][3];
            o.x = (a0 / (1.f + expf(-a0))) * acc3[i][0];
            o.y = (a1 / (1.f + expf(-a1))) * acc3[i][1];
            o.z = (a2 / (1.f + expf(-a2))) * acc3[i][2];
            o.w = (a3 / (1.f + expf(-a3))) * acc3[i][3];
            *(float4*)hp = o;
        }
    }
}

// ---------------- 4) GEMM2: out[tok] += w * (h @ w2[e]) ----------------------
// BM=128, BN=128, BK=8, 256 threads, 8x8 per thread, double buffer.
// Scatter via atomicAdd: exactly two commutative adds per out element.
#define BM2 128
#define BN2 128
#define BK2 8

__global__ void __launch_bounds__(256, 2)
moe_gemm2_kernel(const float* __restrict__ W2, float* __restrict__ Out) {
    const int e   = blockIdx.z;
    const int cnt = g_counts[e];
    const int m0  = blockIdx.y * BM2;
    if (m0 >= cnt) return;
    const int n0  = blockIdx.x * BN2;
    const int tid = threadIdx.x;

    __shared__ float As[2][BK2][BM2];
    __shared__ float Bs[2][BK2][BN2];
    __shared__ int   s_tok[BM2];
    __shared__ float s_w  [BM2];

    if (tid < BM2) {
        int  r = m0 + tid;
        bool v = r < cnt;
        s_tok[tid] = v ? g_tok  [e * CAP + r] : 0;
        s_w  [tid] = v ? g_wlist[e * CAP + r] : 0.f;
    }

    const float* Ap = g_h + ((size_t)e * CAP + m0) * I_DIM;
    const float* Bp = W2 + (size_t)e * I_DIM * H_DIM + n0;

    const int ar  = tid & 127;
    const int akq = tid >> 7;       // 0/1 (row has 2 float4 for BK2=8)
    const int bk  = tid >> 5;       // 0..7
    const int bn  = (tid & 31) * 4; // 0..124

    const int ty = tid >> 4;
    const int tx = tid & 15;

    float acc[8][8];
#pragma unroll
    for (int i = 0; i < 8; ++i)
#pragma unroll
        for (int j = 0; j < 8; ++j) acc[i][j] = 0.f;

    float4 av, bv;
    av = *(const float4*)(Ap + (size_t)ar * I_DIM + akq * 4);
    bv = *(const float4*)(Bp + (size_t)bk * H_DIM + bn);
    As[0][akq*4+0][ar] = av.x; As[0][akq*4+1][ar] = av.y;
    As[0][akq*4+2][ar] = av.z; As[0][akq*4+3][ar] = av.w;
    *(float4*)&Bs[0][bk][bn] = bv;
    __syncthreads();

    const int KT = I_DIM / BK2;   // 512
    for (int kt = 0; kt < KT; ++kt) {
        const int buf = kt & 1;
        if (kt + 1 < KT) {
            const int k1 = (kt + 1) * BK2;
            av = *(const float4*)(Ap + (size_t)ar * I_DIM + k1 + akq * 4);
            bv = *(const float4*)(Bp + (size_t)(k1 + bk) * H_DIM + bn);
        }
#pragma unroll
        for (int kk = 0; kk < BK2; ++kk) {
            float4 a03 = *(const float4*)&As[buf][kk][ty * 8];
            float4 a47 = *(const float4*)&As[buf][kk][ty * 8 + 4];
            float4 b03 = *(const float4*)&Bs[buf][kk][tx * 8];
            float4 b47 = *(const float4*)&Bs[buf][kk][tx * 8 + 4];
            float a[8] = {a03.x,a03.y,a03.z,a03.w,a47.x,a47.y,a47.z,a47.w};
            float b[8] = {b03.x,b03.y,b03.z,b03.w,b47.x,b47.y,b47.z,b47.w};
#pragma unroll
            for (int i = 0; i < 8; ++i)
#pragma unroll
                for (int j = 0; j < 8; ++j)
                    acc[i][j] = fmaf(a[i], b[j], acc[i][j]);
        }
        if (kt + 1 < KT) {
            const int nb = buf ^ 1;
            As[nb][akq*4+0][ar] = av.x; As[nb][akq*4+1][ar] = av.y;
            As[nb][akq*4+2][ar] = av.z; As[nb][akq*4+3][ar] = av.w;
            *(float4*)&Bs[nb][bk][bn] = bv;
        }
        __syncthreads();
    }

#pragma unroll
    for (int i = 0; i < 8; ++i) {
        const int r = ty * 8 + i;
        if (m0 + r < cnt) {
            const float w  = s_w[r];
            float*      op = Out + (size_t)s_tok[r] * H_DIM + n0 + tx * 8;
#pragma unroll
            for (int j = 0; j < 8; ++j)
                atomicAdd(op + j, acc[i][j] * w);
        }
    }
}

// ---------------- launch ----------------------------------------------------
extern "C" void kernel_launch(void* const* d_in, const int* in_sizes, int n_in,
                              void* d_out, int out_size) {
    const float* x  = (const float*)d_in[0];
    const float* gw = (const float*)d_in[1];
    const float* w1 = (const float*)d_in[2];
    const float* w3 = (const float*)d_in[3];
    const float* w2 = (const float*)d_in[4];
    float* out = (float*)d_out;
    const int T = in_sizes[0] / H_DIM;

    cudaMemsetAsync(d_out, 0, (size_t)out_size * sizeof(float), 0);
    router_kernel<<<(T + 7) / 8, 256>>>(x, gw, T);
    build_lists_kernel<<<E_NUM, 256>>>(T);
    dim3 g1(I_DIM / BN1, (T + BM1 - 1) / BM1, E_NUM);
    moe_gemm1_kernel<<<g1, 256>>>(x, w1, w3);
    dim3 g2(H_DIM / BN2, (T + BM2 - 1) / BM2, E_NUM);
    moe_gemm2_kernel<<<g2, 256>>>(w2, out);
}

// round 13
// speedup vs baseline: 1.9856x; 1.9825x over previous
#include <cuda_runtime.h>
#include <cuda_bf16.h>
#include <math.h>
#include <stdint.h>

#define H_DIM 1024
#define E_NUM 8
#define I_DIM 4096
#define T_MAX 8192
#define SLOTS (2*T_MAX)

// ---------------- device scratch (no allocations allowed) -------------------
__device__ int   g_top_idx[T_MAX*2];
__device__ float g_top_w  [T_MAX*2];
__device__ int   g_counts [E_NUM];
__device__ int   g_off    [E_NUM];
__device__ int   g_tok    [E_NUM*T_MAX];
__device__ float g_wlist  [E_NUM*T_MAX];
__device__ __nv_bfloat16 g_xhi [(size_t)T_MAX*H_DIM];
__device__ __nv_bfloat16 g_xlo [(size_t)T_MAX*H_DIM];
__device__ __nv_bfloat16 g_w1hi[(size_t)E_NUM*I_DIM*H_DIM]; // [E][I][H] K-major
__device__ __nv_bfloat16 g_w1lo[(size_t)E_NUM*I_DIM*H_DIM];
__device__ __nv_bfloat16 g_w3hi[(size_t)E_NUM*I_DIM*H_DIM];
__device__ __nv_bfloat16 g_w3lo[(size_t)E_NUM*I_DIM*H_DIM];
__device__ __nv_bfloat16 g_w2hi[(size_t)E_NUM*H_DIM*I_DIM]; // [E][H][I] K-major
__device__ __nv_bfloat16 g_w2lo[(size_t)E_NUM*H_DIM*I_DIM];
__device__ __nv_bfloat16 g_hhi [(size_t)(SLOTS+128)*I_DIM];
__device__ __nv_bfloat16 g_hlo [(size_t)(SLOTS+128)*I_DIM];

// ---------------- PTX helpers (baseline sm_80 features only) -----------------
__device__ __forceinline__ uint32_t smem_u32(const void* p){
    uint32_t a; asm("{ .reg .u64 t; cvta.to.shared.u64 t, %1; cvt.u32.u64 %0, t; }":"=r"(a):"l"(p)); return a;
}
__device__ __forceinline__ void cp16(uint32_t s, const void* g){
    uint64_t ga; asm("cvta.to.global.u64 %0, %1;" : "=l"(ga) : "l"(g));
    asm volatile("cp.async.cg.shared.global [%0], [%1], 16;" :: "r"(s), "l"(ga) : "memory");
}
#define CP_COMMIT() asm volatile("cp.async.commit_group;":::"memory")
#define CP_WAIT1()  asm volatile("cp.async.wait_group 1;":::"memory")
#define CP_WAIT0()  asm volatile("cp.async.wait_group 0;":::"memory")

__device__ __forceinline__ void ldsm4(uint32_t* r, uint32_t a){
    asm volatile("ldmatrix.sync.aligned.m8n8.x4.shared.b16 {%0,%1,%2,%3}, [%4];"
        : "=r"(r[0]),"=r"(r[1]),"=r"(r[2]),"=r"(r[3]) : "r"(a));
}
__device__ __forceinline__ void ldsm2(uint32_t* r, uint32_t a){
    asm volatile("ldmatrix.sync.aligned.m8n8.x2.shared.b16 {%0,%1}, [%2];"
        : "=r"(r[0]),"=r"(r[1]) : "r"(a));
}
__device__ __forceinline__ void mma_bf16(float* c, const uint32_t* a, const uint32_t* b){
    asm volatile("mma.sync.aligned.m16n8k16.row.col.f32.bf16.bf16.f32 "
        "{%0,%1,%2,%3}, {%4,%5,%6,%7}, {%8,%9}, {%0,%1,%2,%3};"
        : "+f"(c[0]),"+f"(c[1]),"+f"(c[2]),"+f"(c[3])
        : "r"(a[0]),"r"(a[1]),"r"(a[2]),"r"(a[3]), "r"(b[0]),"r"(b[1]));
}

// ---------------- router + routing lists (unchanged, proven) -----------------
__global__ void router_kernel(const float* __restrict__ X, const float* __restrict__ GW, int T){
    int t=(blockIdx.x*blockDim.x+threadIdx.x)>>5, lane=threadIdx.x&31;
    if(t>=T) return;
    const float* xr=X+(size_t)t*H_DIM;
    float acc[E_NUM];
#pragma unroll
    for(int e=0;e<E_NUM;++e) acc[e]=0.f;
    for(int k=lane;k<H_DIM;k+=32){
        float xv=__ldg(xr+k);
        float4 g0=*(const float4*)(GW+(size_t)k*E_NUM), g1=*(const float4*)(GW+(size_t)k*E_NUM+4);
        acc[0]+=xv*g0.x; acc[1]+=xv*g0.y; acc[2]+=xv*g0.z; acc[3]+=xv*g0.w;
        acc[4]+=xv*g1.x; acc[5]+=xv*g1.y; acc[6]+=xv*g1.z; acc[7]+=xv*g1.w;
    }
#pragma unroll
    for(int o=16;o>0;o>>=1)
#pragma unroll
        for(int e=0;e<E_NUM;++e) acc[e]+=__shfl_xor_sync(0xffffffffu,acc[e],o);
    if(lane==0){
        int i1=0;
#pragma unroll
        for(int e=1;e<E_NUM;++e) if(acc[e]>acc[i1]) i1=e;
        int i2=(i1==0)?1:0;
#pragma unroll
        for(int e=0;e<E_NUM;++e) if(e!=i1&&acc[e]>acc[i2]) i2=e;
        float d=expf(acc[i2]-acc[i1]);
        g_top_idx[2*t]=i1;   g_top_w[2*t]=1.f/(1.f+d);
        g_top_idx[2*t+1]=i2; g_top_w[2*t+1]=d/(1.f+d);
    }
}
__global__ void build_lists_kernel(int T){
    const int e=blockIdx.x, tid=threadIdx.x, lane=tid&31, wid=tid>>5;
    __shared__ int s_wsum[8]; __shared__ int s_base;
    if(tid==0) s_base=0;
    __syncthreads();
    for(int st=0;st<T;st+=256){
        int t=st+tid, flag=0; float w=0.f;
        if(t<T){
            if(g_top_idx[2*t]==e){flag=1;w=g_top_w[2*t];}
            else if(g_top_idx[2*t+1]==e){flag=1;w=g_top_w[2*t+1];}
        }
        unsigned m=__ballot_sync(0xffffffffu,flag);
        if(lane==0) s_wsum[wid]=__popc(m);
        __syncthreads();
        int off=s_base;
        for(int i=0;i<wid;++i) off+=s_wsum[i];
        int pos=off+__popc(m&((1u<<lane)-1u));
        if(flag){ g_tok[e*T_MAX+pos]=t; g_wlist[e*T_MAX+pos]=w; }
        __syncthreads();
        if(tid==0){ int tt=0;
#pragma unroll
            for(int i=0;i<8;++i) tt+=s_wsum[i];
            s_base+=tt; }
        __syncthreads();
    }
    if(tid==0) g_counts[e]=s_base;
}
__global__ void scan_counts_kernel(){
    if(threadIdx.x==0){ int s=0;
#pragma unroll
        for(int e=0;e<E_NUM;++e){ g_off[e]=s; s+=g_counts[e]; } }
}

// ---------------- bf16 hi/lo split + K-major transposes ----------------------
__global__ void split_x_kernel(const float* __restrict__ x, int n){
    int i=blockIdx.x*blockDim.x+threadIdx.x;
    if(i>=n) return;
    float v=x[i];
    __nv_bfloat16 h=__float2bfloat16_rn(v);
    g_xhi[i]=h; g_xlo[i]=__float2bfloat16_rn(v-__bfloat162float(h));
}
__global__ void transpose_split_kernel(const float* __restrict__ src, int R, int C, int which){
    __nv_bfloat16 *dhi,*dlo;
    if(which==0){dhi=g_w1hi;dlo=g_w1lo;} else if(which==1){dhi=g_w3hi;dlo=g_w3lo;}
    else {dhi=g_w2hi;dlo=g_w2lo;}
    __shared__ float t[32][33];
    size_t base=(size_t)blockIdx.z*R*C;
    int c0=blockIdx.x*32, r0=blockIdx.y*32;
#pragma unroll
    for(int i=threadIdx.y;i<32;i+=8)
        t[i][threadIdx.x]=src[base+(size_t)(r0+i)*C+c0+threadIdx.x];
    __syncthreads();
#pragma unroll
    for(int i=threadIdx.y;i<32;i+=8){
        float v=t[threadIdx.x][i];
        __nv_bfloat16 h=__float2bfloat16_rn(v);
        size_t o=base+(size_t)(c0+i)*R+r0+threadIdx.x;
        dhi[o]=h; dlo[o]=__float2bfloat16_rn(v-__bfloat162float(h));
    }
}

// ---------------- GEMM1 (mma.sync): h = silu(x@w1)*(x@w3) --------------------
// BM=128, BN=64 (dual matrices), BK=32. SMEM rows padded to 80B (conflict-free
// ldmatrix). 2-stage cp.async pipeline. bf16x3: AhBh + AhBl + AlBh.
#define ROWB 80
#define A1_OFF(st,t) (512   + ((st)*2+(t))*10240)   // 128 rows * 80B
#define B1_OFF(st,t) (41472 + ((st)*4+(t))*5120)    // 64 rows * 80B
#define G1_SMEM 82432

__global__ void __launch_bounds__(256,1) moe_gemm1_mma(){
    const int e=blockIdx.z, cnt=g_counts[e];
    const int m0=blockIdx.y*128; if(m0>=cnt) return;
    const int n0=blockIdx.x*64;
    const int tid=threadIdx.x, lane=tid&31, wid=tid>>5;
    const int wm=wid&3, wn=wid>>2;
    extern __shared__ char sm[];
    uint32_t sb=smem_u32(sm);
    int* s_tok=(int*)sm;
    if(tid<128){ int r=m0+tid; s_tok[tid]=g_tok[e*T_MAX+(r<cnt?r:cnt-1)]; }
    __syncthreads();

    const size_t ebase=(size_t)e*I_DIM*H_DIM;
    const __nv_bfloat16* bsrc[4]={ g_w1hi+ebase+(size_t)n0*H_DIM, g_w1lo+ebase+(size_t)n0*H_DIM,
                                   g_w3hi+ebase+(size_t)n0*H_DIM, g_w3lo+ebase+(size_t)n0*H_DIM };
    const int c8=(tid&3)*8, c16=(tid&3)*16, lrow=tid>>2;

    auto load_stage=[&](int k0,int st){
#pragma unroll
        for(int half=0; half<2; ++half){
            int row=lrow+half*64;
            size_t so=(size_t)s_tok[row]*H_DIM + k0 + c8;
            cp16(sb + A1_OFF(st,0) + row*ROWB + c16, g_xhi+so);
            cp16(sb + A1_OFF(st,1) + row*ROWB + c16, g_xlo+so);
        }
#pragma unroll
        for(int t=0;t<4;++t)
            cp16(sb + B1_OFF(st,t) + lrow*ROWB + c16, bsrc[t]+(size_t)lrow*H_DIM + k0 + c8);
        CP_COMMIT();
    };

    float acc1[2][4][4], acc3[2][4][4];
#pragma unroll
    for(int i=0;i<2;++i)
#pragma unroll
    for(int j=0;j<4;++j)
#pragma unroll
    for(int k=0;k<4;++k){ acc1[i][j][k]=0.f; acc3[i][j][k]=0.f; }

    load_stage(0,0);
    const uint32_t a_r=(uint32_t)(wm*32+(lane&15)), a_c=((lane>>4)&1)*16;
    const uint32_t b_r=(uint32_t)(wn*32+(lane&7)),  b_c=((lane>>3)&1)*16;
    const int NCH=H_DIM/32;  // 32
    for(int kt=0;kt<NCH;++kt){
        int buf=kt&1;
        if(kt+1<NCH){ load_stage((kt+1)*32, buf^1); CP_WAIT1(); } else CP_WAIT0();
        __syncthreads();
#pragma unroll
        for(int ks=0;ks<2;++ks){
            uint32_t ah[2][4], al[2][4];
#pragma unroll
            for(int mt=0;mt<2;++mt){
                uint32_t ra=a_r+mt*16;
                ldsm4(ah[mt], sb + A1_OFF(buf,0) + ra*ROWB + ks*32 + a_c);
                ldsm4(al[mt], sb + A1_OFF(buf,1) + ra*ROWB + ks*32 + a_c);
            }
            uint32_t b1h[4][2], b1l[4][2], b3h[4][2], b3l[4][2];
#pragma unroll
            for(int nt=0;nt<4;++nt){
                uint32_t rb=b_r+nt*8;
                ldsm2(b1h[nt], sb + B1_OFF(buf,0) + rb*ROWB + ks*32 + b_c);
                ldsm2(b1l[nt], sb + B1_OFF(buf,1) + rb*ROWB + ks*32 + b_c);
                ldsm2(b3h[nt], sb + B1_OFF(buf,2) + rb*ROWB + ks*32 + b_c);
                ldsm2(b3l[nt], sb + B1_OFF(buf,3) + rb*ROWB + ks*32 + b_c);
            }
#pragma unroll
            for(int mt=0;mt<2;++mt)
#pragma unroll
            for(int nt=0;nt<4;++nt){
                mma_bf16(acc1[mt][nt], ah[mt], b1h[nt]);
                mma_bf16(acc1[mt][nt], ah[mt], b1l[nt]);
                mma_bf16(acc1[mt][nt], al[mt], b1h[nt]);
                mma_bf16(acc3[mt][nt], ah[mt], b3h[nt]);
                mma_bf16(acc3[mt][nt], ah[mt], b3l[nt]);
                mma_bf16(acc3[mt][nt], al[mt], b3h[nt]);
            }
        }
        __syncthreads();
    }

    // SwiGLU epilogue -> split bf16 hi/lo -> g_hhi/g_hlo
    const int eoff=g_off[e];
#pragma unroll
    for(int mt=0;mt<2;++mt)
#pragma unroll
    for(int nt=0;nt<4;++nt){
        int mbase=m0 + wm*32 + mt*16 + (lane>>2);
        int col  =n0 + wn*32 + nt*8 + (lane&3)*2;
#pragma unroll
        for(int h2=0;h2<2;++h2){
            int m=mbase+h2*8;
            if(m<cnt){
                float s0=acc1[mt][nt][h2*2], s1=acc1[mt][nt][h2*2+1];
                float v0=(s0/(1.f+expf(-s0)))*acc3[mt][nt][h2*2];
                float v1=(s1/(1.f+expf(-s1)))*acc3[mt][nt][h2*2+1];
                __nv_bfloat16 h0=__float2bfloat16_rn(v0), h1=__float2bfloat16_rn(v1);
                __nv_bfloat162 hv; hv.x=h0; hv.y=h1;
                __nv_bfloat162 lv;
                lv.x=__float2bfloat16_rn(v0-__bfloat162float(h0));
                lv.y=__float2bfloat16_rn(v1-__bfloat162float(h1));
                size_t o=((size_t)(eoff+m))*I_DIM+col;
                *(__nv_bfloat162*)(g_hhi+o)=hv;
                *(__nv_bfloat162*)(g_hlo+o)=lv;
            }
        }
    }
}

// ---------------- GEMM2 (mma.sync): out[tok] += w*(h@w2) ---------------------
// BM=128, BN=128, BK=32; weighted atomicAdd scatter (2 adds/element total).
#define A2_OFF(st,t) (1024  + ((st)*2+(t))*10240)
#define B2_OFF(st,t) (41984 + ((st)*2+(t))*10240)
#define G2_SMEM 82944

__global__ void __launch_bounds__(256,1) moe_gemm2_mma(float* __restrict__ Out){
    const int e=blockIdx.z, cnt=g_counts[e];
    const int m0=blockIdx.y*128; if(m0>=cnt) return;
    const int n0=blockIdx.x*128;
    const int tid=threadIdx.x, lane=tid&31, wid=tid>>5;
    const int wm=wid&3, wn=wid>>2;
    extern __shared__ char sm[];
    uint32_t sb=smem_u32(sm);
    int*   s_tok=(int*)sm;
    float* s_w  =(float*)(sm+512);
    if(tid<128){
        int r=m0+tid; bool v=r<cnt;
        s_tok[tid]=v?g_tok[e*T_MAX+r]:0;
        s_w  [tid]=v?g_wlist[e*T_MAX+r]:0.f;
    }
    __syncthreads();

    const int slot0=g_off[e]+m0;
    const size_t ebase=(size_t)e*H_DIM*I_DIM;
    const int c8=(tid&3)*8, c16=(tid&3)*16, lrow=tid>>2;

    auto load_stage=[&](int k0,int st){
#pragma unroll
        for(int half=0; half<2; ++half){
            int row=lrow+half*64;
            size_t ao=(size_t)(slot0+row)*I_DIM + k0 + c8;
            cp16(sb + A2_OFF(st,0) + row*ROWB + c16, g_hhi+ao);
            cp16(sb + A2_OFF(st,1) + row*ROWB + c16, g_hlo+ao);
            size_t bo=ebase+(size_t)(n0+row)*I_DIM + k0 + c8;
            cp16(sb + B2_OFF(st,0) + row*ROWB + c16, g_w2hi+bo);
            cp16(sb + B2_OFF(st,1) + row*ROWB + c16, g_w2lo+bo);
        }
        CP_COMMIT();
    };

    float acc[2][8][4];
#pragma unroll
    for(int i=0;i<2;++i)
#pragma unroll
    for(int j=0;j<8;++j)
#pragma unroll
    for(int k=0;k<4;++k) acc[i][j][k]=0.f;

    load_stage(0,0);
    const uint32_t a_r=(uint32_t)(wm*32+(lane&15)), a_c=((lane>>4)&1)*16;
    const uint32_t b_r=(uint32_t)(wn*64+(lane&7)),  b_c=((lane>>3)&1)*16;
    const int NCH=I_DIM/32;  // 128
    for(int kt=0;kt<NCH;++kt){
        int buf=kt&1;
        if(kt+1<NCH){ load_stage((kt+1)*32, buf^1); CP_WAIT1(); } else CP_WAIT0();
        __syncthreads();
#pragma unroll
        for(int ks=0;ks<2;++ks){
            uint32_t ah[2][4], al[2][4];
#pragma unroll
            for(int mt=0;mt<2;++mt){
                uint32_t ra=a_r+mt*16;
                ldsm4(ah[mt], sb + A2_OFF(buf,0) + ra*ROWB + ks*32 + a_c);
                ldsm4(al[mt], sb + A2_OFF(buf,1) + ra*ROWB + ks*32 + a_c);
            }
            uint32_t bh[8][2], bl[8][2];
#pragma unroll
            for(int nt=0;nt<8;++nt){
                uint32_t rb=b_r+nt*8;
                ldsm2(bh[nt], sb + B2_OFF(buf,0) + rb*ROWB + ks*32 + b_c);
                ldsm2(bl[nt], sb + B2_OFF(buf,1) + rb*ROWB + ks*32 + b_c);
            }
#pragma unroll
            for(int mt=0;mt<2;++mt)
#pragma unroll
            for(int nt=0;nt<8;++nt){
                mma_bf16(acc[mt][nt], ah[mt], bh[nt]);
                mma_bf16(acc[mt][nt], ah[mt], bl[nt]);
                mma_bf16(acc[mt][nt], al[mt], bh[nt]);
            }
        }
        __syncthreads();
    }

#pragma unroll
    for(int mt=0;mt<2;++mt)
#pragma unroll
    for(int nt=0;nt<8;++nt){
        int lr0=wm*32+mt*16+(lane>>2);
        int col=n0 + wn*64 + nt*8 + (lane&3)*2;
#pragma unroll
        for(int h2=0;h2<2;++h2){
            int lr=lr0+h2*8;
            if(m0+lr<cnt){
                float w=s_w[lr];
                float* op=Out+(size_t)s_tok[lr]*H_DIM+col;
                atomicAdd(op,   acc[mt][nt][h2*2]  *w);
                atomicAdd(op+1, acc[mt][nt][h2*2+1]*w);
            }
        }
    }
}

// ---------------- launch ------------------------------------------------------
extern "C" void kernel_launch(void* const* d_in, const int* in_sizes, int n_in,
                              void* d_out, int out_size){
    const float* x =(const float*)d_in[0];
    const float* gw=(const float*)d_in[1];
    const float* w1=(const float*)d_in[2];
    const float* w3=(const float*)d_in[3];
    const float* w2=(const float*)d_in[4];
    float* out=(float*)d_out;
    const int T=in_sizes[0]/H_DIM;

    cudaFuncSetAttribute(moe_gemm1_mma, cudaFuncAttributeMaxDynamicSharedMemorySize, G1_SMEM);
    cudaFuncSetAttribute(moe_gemm2_mma, cudaFuncAttributeMaxDynamicSharedMemorySize, G2_SMEM);

    cudaMemsetAsync(d_out,0,(size_t)out_size*sizeof(float),0);
    router_kernel<<<(T+7)/8,256>>>(x,gw,T);
    build_lists_kernel<<<E_NUM,256>>>(T);
    scan_counts_kernel<<<1,32>>>();
    split_x_kernel<<<(T*H_DIM+255)/256,256>>>(x, T*H_DIM);
    dim3 tb(32,8);
    transpose_split_kernel<<<dim3(I_DIM/32,H_DIM/32,E_NUM),tb>>>(w1,H_DIM,I_DIM,0);
    transpose_split_kernel<<<dim3(I_DIM/32,H_DIM/32,E_NUM),tb>>>(w3,H_DIM,I_DIM,1);
    transpose_split_kernel<<<dim3(H_DIM/32,I_DIM/32,E_NUM),tb>>>(w2,I_DIM,H_DIM,2);
    const int mt=(T+127)/128;
    moe_gemm1_mma<<<dim3(I_DIM/64,  mt, E_NUM),256,G1_SMEM>>>();
    moe_gemm2_mma<<<dim3(H_DIM/128, mt, E_NUM),256,G2_SMEM>>>(out);
}

// round 14
// speedup vs baseline: 2.5516x; 1.2851x over previous
#include <cuda_runtime.h>
#include <cuda_bf16.h>
#include <math.h>
#include <stdint.h>

#define H_DIM 1024
#define E_NUM 8
#define I_DIM 4096
#define T_MAX 8192
#define SLOTS (2*T_MAX)

// ---------------- device scratch (no allocations allowed) -------------------
__device__ int   g_top_idx[T_MAX*2];
__device__ float g_top_w  [T_MAX*2];
__device__ int   g_counts [E_NUM];
__device__ int   g_off    [E_NUM];
__device__ int   g_tok    [E_NUM*T_MAX];
__device__ float g_wlist  [E_NUM*T_MAX];
__device__ __nv_bfloat16 g_xhi [(size_t)T_MAX*H_DIM];
__device__ __nv_bfloat16 g_xlo [(size_t)T_MAX*H_DIM];
__device__ __nv_bfloat16 g_w1hi[(size_t)E_NUM*I_DIM*H_DIM]; // [E][I][H] K-major
__device__ __nv_bfloat16 g_w1lo[(size_t)E_NUM*I_DIM*H_DIM];
__device__ __nv_bfloat16 g_w3hi[(size_t)E_NUM*I_DIM*H_DIM];
__device__ __nv_bfloat16 g_w3lo[(size_t)E_NUM*I_DIM*H_DIM];
__device__ __nv_bfloat16 g_w2hi[(size_t)E_NUM*H_DIM*I_DIM]; // [E][H][I] K-major
__device__ __nv_bfloat16 g_w2lo[(size_t)E_NUM*H_DIM*I_DIM];
__device__ __nv_bfloat16 g_hhi [(size_t)(SLOTS+128)*I_DIM];
__device__ __nv_bfloat16 g_hlo [(size_t)(SLOTS+128)*I_DIM];

// ---------------- PTX helpers (baseline sm_80 features only) -----------------
__device__ __forceinline__ uint32_t smem_u32(const void* p){
    uint32_t a; asm("{ .reg .u64 t; cvta.to.shared.u64 t, %1; cvt.u32.u64 %0, t; }":"=r"(a):"l"(p)); return a;
}
__device__ __forceinline__ void cp16(uint32_t s, const void* g){
    uint64_t ga; asm("cvta.to.global.u64 %0, %1;" : "=l"(ga) : "l"(g));
    asm volatile("cp.async.cg.shared.global [%0], [%1], 16;" :: "r"(s), "l"(ga) : "memory");
}
#define CP_COMMIT() asm volatile("cp.async.commit_group;":::"memory")
#define CP_WAIT0()  asm volatile("cp.async.wait_group 0;":::"memory")

__device__ __forceinline__ void ldsm4(uint32_t* r, uint32_t a){
    asm volatile("ldmatrix.sync.aligned.m8n8.x4.shared.b16 {%0,%1,%2,%3}, [%4];"
        : "=r"(r[0]),"=r"(r[1]),"=r"(r[2]),"=r"(r[3]) : "r"(a));
}
__device__ __forceinline__ void mma_bf16(float* c, const uint32_t* a, const uint32_t* b){
    asm volatile("mma.sync.aligned.m16n8k16.row.col.f32.bf16.bf16.f32 "
        "{%0,%1,%2,%3}, {%4,%5,%6,%7}, {%8,%9}, {%0,%1,%2,%3};"
        : "+f"(c[0]),"+f"(c[1]),"+f"(c[2]),"+f"(c[3])
        : "r"(a[0]),"r"(a[1]),"r"(a[2]),"r"(a[3]), "r"(b[0]),"r"(b[1]));
}

// ---------------- router + routing lists (unchanged, proven) -----------------
__global__ void router_kernel(const float* __restrict__ X, const float* __restrict__ GW, int T){
    int t=(blockIdx.x*blockDim.x+threadIdx.x)>>5, lane=threadIdx.x&31;
    if(t>=T) return;
    const float* xr=X+(size_t)t*H_DIM;
    float acc[E_NUM];
#pragma unroll
    for(int e=0;e<E_NUM;++e) acc[e]=0.f;
    for(int k=lane;k<H_DIM;k+=32){
        float xv=__ldg(xr+k);
        float4 g0=*(const float4*)(GW+(size_t)k*E_NUM), g1=*(const float4*)(GW+(size_t)k*E_NUM+4);
        acc[0]+=xv*g0.x; acc[1]+=xv*g0.y; acc[2]+=xv*g0.z; acc[3]+=xv*g0.w;
        acc[4]+=xv*g1.x; acc[5]+=xv*g1.y; acc[6]+=xv*g1.z; acc[7]+=xv*g1.w;
    }
#pragma unroll
    for(int o=16;o>0;o>>=1)
#pragma unroll
        for(int e=0;e<E_NUM;++e) acc[e]+=__shfl_xor_sync(0xffffffffu,acc[e],o);
    if(lane==0){
        int i1=0;
#pragma unroll
        for(int e=1;e<E_NUM;++e) if(acc[e]>acc[i1]) i1=e;
        int i2=(i1==0)?1:0;
#pragma unroll
        for(int e=0;e<E_NUM;++e) if(e!=i1&&acc[e]>acc[i2]) i2=e;
        float d=expf(acc[i2]-acc[i1]);
        g_top_idx[2*t]=i1;   g_top_w[2*t]=1.f/(1.f+d);
        g_top_idx[2*t+1]=i2; g_top_w[2*t+1]=d/(1.f+d);
    }
}
__global__ void build_lists_kernel(int T){
    const int e=blockIdx.x, tid=threadIdx.x, lane=tid&31, wid=tid>>5;
    __shared__ int s_wsum[8]; __shared__ int s_base;
    if(tid==0) s_base=0;
    __syncthreads();
    for(int st=0;st<T;st+=256){
        int t=st+tid, flag=0; float w=0.f;
        if(t<T){
            if(g_top_idx[2*t]==e){flag=1;w=g_top_w[2*t];}
            else if(g_top_idx[2*t+1]==e){flag=1;w=g_top_w[2*t+1];}
        }
        unsigned m=__ballot_sync(0xffffffffu,flag);
        if(lane==0) s_wsum[wid]=__popc(m);
        __syncthreads();
        int off=s_base;
        for(int i=0;i<wid;++i) off+=s_wsum[i];
        int pos=off+__popc(m&((1u<<lane)-1u));
        if(flag){ g_tok[e*T_MAX+pos]=t; g_wlist[e*T_MAX+pos]=w; }
        __syncthreads();
        if(tid==0){ int tt=0;
#pragma unroll
            for(int i=0;i<8;++i) tt+=s_wsum[i];
            s_base+=tt; }
        __syncthreads();
    }
    if(tid==0) g_counts[e]=s_base;
}
__global__ void scan_counts_kernel(){
    if(threadIdx.x==0){ int s=0;
#pragma unroll
        for(int e=0;e<E_NUM;++e){ g_off[e]=s; s+=g_counts[e]; } }
}

// ---------------- bf16 hi/lo split + K-major transposes ----------------------
__global__ void split_x_kernel(const float* __restrict__ x, int n){
    int i=blockIdx.x*blockDim.x+threadIdx.x;
    if(i>=n) return;
    float v=x[i];
    __nv_bfloat16 h=__float2bfloat16_rn(v);
    g_xhi[i]=h; g_xlo[i]=__float2bfloat16_rn(v-__bfloat162float(h));
}
// [R][C] fp32 -> [C][R] bf16 hi/lo; tile 64(R) x 32(C); packed bf16x2 stores.
__global__ void transpose_split_kernel(const float* __restrict__ src, int R, int C, int which){
    __nv_bfloat16 *dhi,*dlo;
    if(which==0){dhi=g_w1hi;dlo=g_w1lo;} else if(which==1){dhi=g_w3hi;dlo=g_w3lo;}
    else {dhi=g_w2hi;dlo=g_w2lo;}
    __shared__ float s[64][33];
    size_t base=(size_t)blockIdx.z*R*C;
    int r0=blockIdx.y*64, c0=blockIdx.x*32;
    int tx=threadIdx.x, ty=threadIdx.y;  // 32x8
#pragma unroll
    for(int i=ty;i<64;i+=8)
        s[i][tx]=src[base+(size_t)(r0+i)*C+c0+tx];
    __syncthreads();
#pragma unroll
    for(int i=ty;i<32;i+=8){
        float v0=s[2*tx][i], v1=s[2*tx+1][i];
        __nv_bfloat16 h0=__float2bfloat16_rn(v0), h1=__float2bfloat16_rn(v1);
        __nv_bfloat162 hv; hv.x=h0; hv.y=h1;
        __nv_bfloat162 lv;
        lv.x=__float2bfloat16_rn(v0-__bfloat162float(h0));
        lv.y=__float2bfloat16_rn(v1-__bfloat162float(h1));
        size_t o=base+(size_t)(c0+i)*R+r0+2*tx;
        *(__nv_bfloat162*)(dhi+o)=hv;
        *(__nv_bfloat162*)(dlo+o)=lv;
    }
}

// ---------------- GEMM1 (mma.sync): h = silu(x@w1)*(x@w3) --------------------
// BM=128, BN=64 (dual outputs), BK=32, bf16x3. 2-stage cp.async, 1 sync/kt,
// 2 CTAs/SM. SMEM rows padded to 80B (conflict-free ldmatrix).
#define ROWB 80
#define A1_OFF(st,t) (512   + ((st)*2+(t))*10240)   // 128 rows * 80B
#define B1_OFF(st,t) (41472 + ((st)*4+(t))*5120)    // 64 rows * 80B
#define G1_SMEM 82432

__global__ void __launch_bounds__(256,2) moe_gemm1_mma(){
    const int e=blockIdx.z, cnt=g_counts[e];
    const int m0=blockIdx.y*128; if(m0>=cnt) return;
    const int n0=blockIdx.x*64;
    const int tid=threadIdx.x, lane=tid&31, wid=tid>>5;
    const int wm=wid&3, wn=wid>>2;
    extern __shared__ char sm[];
    uint32_t sb=smem_u32(sm);
    int* s_tok=(int*)sm;
    if(tid<128){ int r=m0+tid; s_tok[tid]=g_tok[e*T_MAX+(r<cnt?r:cnt-1)]; }
    __syncthreads();

    const size_t ebase=(size_t)e*I_DIM*H_DIM;
    const __nv_bfloat16* bsrc[4]={ g_w1hi+ebase+(size_t)n0*H_DIM, g_w1lo+ebase+(size_t)n0*H_DIM,
                                   g_w3hi+ebase+(size_t)n0*H_DIM, g_w3lo+ebase+(size_t)n0*H_DIM };
    const int c8=(tid&3)*8, c16=(tid&3)*16, lrow=tid>>2;

    auto load_stage=[&](int k0,int st){
#pragma unroll
        for(int half=0; half<2; ++half){
            int row=lrow+half*64;
            size_t so=(size_t)s_tok[row]*H_DIM + k0 + c8;
            cp16(sb + A1_OFF(st,0) + row*ROWB + c16, g_xhi+so);
            cp16(sb + A1_OFF(st,1) + row*ROWB + c16, g_xlo+so);
        }
#pragma unroll
        for(int t=0;t<4;++t)
            cp16(sb + B1_OFF(st,t) + lrow*ROWB + c16, bsrc[t]+(size_t)lrow*H_DIM + k0 + c8);
        CP_COMMIT();
    };

    float acc1[2][4][4], acc3[2][4][4];
#pragma unroll
    for(int i=0;i<2;++i)
#pragma unroll
    for(int j=0;j<4;++j)
#pragma unroll
    for(int k=0;k<4;++k){ acc1[i][j][k]=0.f; acc3[i][j][k]=0.f; }

    load_stage(0,0);
    const uint32_t a_r=(uint32_t)(wm*32+(lane&15)), a_c=((lane>>4)&1)*16;
    // B ldsm4 address: 4 mats = {nt:k0, nt:k1, nt+1:k0, nt+1:k1}
    const uint32_t b_row8=(uint32_t)((lane&7) + ((lane>>4)&1)*8);
    const uint32_t b_col =((lane>>3)&1)*16;
    const int NCH=H_DIM/32;  // 32
    for(int kt=0;kt<NCH;++kt){
        const int buf=kt&1;
        CP_WAIT0();
        __syncthreads();
        if(kt+1<NCH) load_stage((kt+1)*32, buf^1);
#pragma unroll
        for(int ks=0;ks<2;++ks){
            uint32_t ah[2][4], al[2][4];
#pragma unroll
            for(int mt=0;mt<2;++mt){
                uint32_t ra=a_r+mt*16;
                ldsm4(ah[mt], sb + A1_OFF(buf,0) + ra*ROWB + ks*32 + a_c);
                ldsm4(al[mt], sb + A1_OFF(buf,1) + ra*ROWB + ks*32 + a_c);
            }
#pragma unroll
            for(int ntp=0;ntp<2;++ntp){
                uint32_t boff=(uint32_t)((wn*32+ntp*16+b_row8)*ROWB + ks*32 + b_col);
                uint32_t q1h[4],q1l[4],q3h[4],q3l[4];
                ldsm4(q1h, sb + B1_OFF(buf,0) + boff);
                ldsm4(q1l, sb + B1_OFF(buf,1) + boff);
                ldsm4(q3h, sb + B1_OFF(buf,2) + boff);
                ldsm4(q3l, sb + B1_OFF(buf,3) + boff);
#pragma unroll
                for(int mt=0;mt<2;++mt){
#pragma unroll
                    for(int half=0;half<2;++half){
                        int nt=ntp*2+half;
                        mma_bf16(acc1[mt][nt], ah[mt], q1h+half*2);
                        mma_bf16(acc1[mt][nt], ah[mt], q1l+half*2);
                        mma_bf16(acc1[mt][nt], al[mt], q1h+half*2);
                        mma_bf16(acc3[mt][nt], ah[mt], q3h+half*2);
                        mma_bf16(acc3[mt][nt], ah[mt], q3l+half*2);
                        mma_bf16(acc3[mt][nt], al[mt], q3h+half*2);
                    }
                }
            }
        }
        __syncthreads();
    }

    // SwiGLU epilogue -> split bf16 hi/lo -> g_hhi/g_hlo
    const int eoff=g_off[e];
#pragma unroll
    for(int mt=0;mt<2;++mt)
#pragma unroll
    for(int nt=0;nt<4;++nt){
        int mbase=m0 + wm*32 + mt*16 + (lane>>2);
        int col  =n0 + wn*32 + nt*8 + (lane&3)*2;
#pragma unroll
        for(int h2=0;h2<2;++h2){
            int m=mbase+h2*8;
            if(m<cnt){
                float s0=acc1[mt][nt][h2*2], s1=acc1[mt][nt][h2*2+1];
                float v0=(s0/(1.f+expf(-s0)))*acc3[mt][nt][h2*2];
                float v1=(s1/(1.f+expf(-s1)))*acc3[mt][nt][h2*2+1];
                __nv_bfloat16 h0=__float2bfloat16_rn(v0), h1=__float2bfloat16_rn(v1);
                __nv_bfloat162 hv; hv.x=h0; hv.y=h1;
                __nv_bfloat162 lv;
                lv.x=__float2bfloat16_rn(v0-__bfloat162float(h0));
                lv.y=__float2bfloat16_rn(v1-__bfloat162float(h1));
                size_t o=((size_t)(eoff+m))*I_DIM+col;
                *(__nv_bfloat162*)(g_hhi+o)=hv;
                *(__nv_bfloat162*)(g_hlo+o)=lv;
            }
        }
    }
}

// ---------------- GEMM2 (mma.sync): out[tok] += w*(h@w2) ---------------------
// BM=128, BN=128, BK=32; weighted atomicAdd scatter (2 adds/element total).
#define A2_OFF(st,t) (1024  + ((st)*2+(t))*10240)
#define B2_OFF(st,t) (41984 + ((st)*2+(t))*10240)
#define G2_SMEM 82944

__global__ void __launch_bounds__(256,2) moe_gemm2_mma(float* __restrict__ Out){
    const int e=blockIdx.z, cnt=g_counts[e];
    const int m0=blockIdx.y*128; if(m0>=cnt) return;
    const int n0=blockIdx.x*128;
    const int tid=threadIdx.x, lane=tid&31, wid=tid>>5;
    const int wm=wid&3, wn=wid>>2;
    extern __shared__ char sm[];
    uint32_t sb=smem_u32(sm);
    int*   s_tok=(int*)sm;
    float* s_w  =(float*)(sm+512);
    if(tid<128){
        int r=m0+tid; bool v=r<cnt;
        s_tok[tid]=v?g_tok[e*T_MAX+r]:0;
        s_w  [tid]=v?g_wlist[e*T_MAX+r]:0.f;
    }
    __syncthreads();

    const int slot0=g_off[e]+m0;
    const size_t ebase=(size_t)e*H_DIM*I_DIM;
    const int c8=(tid&3)*8, c16=(tid&3)*16, lrow=tid>>2;

    auto load_stage=[&](int k0,int st){
#pragma unroll
        for(int half=0; half<2; ++half){
            int row=lrow+half*64;
            size_t ao=(size_t)(slot0+row)*I_DIM + k0 + c8;
            cp16(sb + A2_OFF(st,0) + row*ROWB + c16, g_hhi+ao);
            cp16(sb + A2_OFF(st,1) + row*ROWB + c16, g_hlo+ao);
            size_t bo=ebase+(size_t)(n0+row)*I_DIM + k0 + c8;
            cp16(sb + B2_OFF(st,0) + row*ROWB + c16, g_w2hi+bo);
            cp16(sb + B2_OFF(st,1) + row*ROWB + c16, g_w2lo+bo);
        }
        CP_COMMIT();
    };

    float acc[2][8][4];
#pragma unroll
    for(int i=0;i<2;++i)
#pragma unroll
    for(int j=0;j<8;++j)
#pragma unroll
    for(int k=0;k<4;++k) acc[i][j][k]=0.f;

    load_stage(0,0);
    const uint32_t a_r=(uint32_t)(wm*32+(lane&15)), a_c=((lane>>4)&1)*16;
    const uint32_t b_row8=(uint32_t)((lane&7) + ((lane>>4)&1)*8);
    const uint32_t b_col =((lane>>3)&1)*16;
    const int NCH=I_DIM/32;  // 128
    for(int kt=0;kt<NCH;++kt){
        const int buf=kt&1;
        CP_WAIT0();
        __syncthreads();
        if(kt+1<NCH) load_stage((kt+1)*32, buf^1);
#pragma unroll
        for(int ks=0;ks<2;++ks){
            uint32_t ah[2][4], al[2][4];
#pragma unroll
            for(int mt=0;mt<2;++mt){
                uint32_t ra=a_r+mt*16;
                ldsm4(ah[mt], sb + A2_OFF(buf,0) + ra*ROWB + ks*32 + a_c);
                ldsm4(al[mt], sb + A2_OFF(buf,1) + ra*ROWB + ks*32 + a_c);
            }
#pragma unroll
            for(int ntp=0;ntp<4;++ntp){
                uint32_t boff=(uint32_t)((wn*64+ntp*16+b_row8)*ROWB + ks*32 + b_col);
                uint32_t qh[4], ql[4];
                ldsm4(qh, sb + B2_OFF(buf,0) + boff);
                ldsm4(ql, sb + B2_OFF(buf,1) + boff);
#pragma unroll
                for(int mt=0;mt<2;++mt){
#pragma unroll
                    for(int half=0;half<2;++half){
                        int nt=ntp*2+half;
                        mma_bf16(acc[mt][nt], ah[mt], qh+half*2);
                        mma_bf16(acc[mt][nt], ah[mt], ql+half*2);
                        mma_bf16(acc[mt][nt], al[mt], qh+half*2);
                    }
                }
            }
        }
        __syncthreads();
    }

#pragma unroll
    for(int mt=0;mt<2;++mt)
#pragma unroll
    for(int nt=0;nt<8;++nt){
        int lr0=wm*32+mt*16+(lane>>2);
        int col=n0 + wn*64 + nt*8 + (lane&3)*2;
#pragma unroll
        for(int h2=0;h2<2;++h2){
            int lr=lr0+h2*8;
            if(m0+lr<cnt){
                float w=s_w[lr];
                float* op=Out+(size_t)s_tok[lr]*H_DIM+col;
                atomicAdd(op,   acc[mt][nt][h2*2]  *w);
                atomicAdd(op+1, acc[mt][nt][h2*2+1]*w);
            }
        }
    }
}

// ---------------- launch ------------------------------------------------------
extern "C" void kernel_launch(void* const* d_in, const int* in_sizes, int n_in,
                              void* d_out, int out_size){
    const float* x =(const float*)d_in[0];
    const float* gw=(const float*)d_in[1];
    const float* w1=(const float*)d_in[2];
    const float* w3=(const float*)d_in[3];
    const float* w2=(const float*)d_in[4];
    float* out=(float*)d_out;
    const int T=in_sizes[0]/H_DIM;

    cudaFuncSetAttribute(moe_gemm1_mma, cudaFuncAttributeMaxDynamicSharedMemorySize, G1_SMEM);
    cudaFuncSetAttribute(moe_gemm2_mma, cudaFuncAttributeMaxDynamicSharedMemorySize, G2_SMEM);

    cudaMemsetAsync(d_out,0,(size_t)out_size*sizeof(float),0);
    router_kernel<<<(T+7)/8,256>>>(x,gw,T);
    build_lists_kernel<<<E_NUM,256>>>(T);
    scan_counts_kernel<<<1,32>>>();
    split_x_kernel<<<(T*H_DIM+255)/256,256>>>(x, T*H_DIM);
    dim3 tb(32,8);
    transpose_split_kernel<<<dim3(I_DIM/32,H_DIM/64,E_NUM),tb>>>(w1,H_DIM,I_DIM,0);
    transpose_split_kernel<<<dim3(I_DIM/32,H_DIM/64,E_NUM),tb>>>(w3,H_DIM,I_DIM,1);
    transpose_split_kernel<<<dim3(H_DIM/32,I_DIM/64,E_NUM),tb>>>(w2,I_DIM,H_DIM,2);
    const int mt=(T+127)/128;
    moe_gemm1_mma<<<dim3(I_DIM/64,  mt, E_NUM),256,G1_SMEM>>>();
    moe_gemm2_mma<<<dim3(H_DIM/128, mt, E_NUM),256,G2_SMEM>>>(out);
}